// round 1
// baseline (speedup 1.0000x reference)
#include <cuda_runtime.h>
#include <math.h>

// Problem constants (fixed by the reference)
#define NSRC  100000
#define NDST  100000
#define NEDGE 1250000
#define DF    64     // D_FEAT
#define HID   64     // HIDDEN
#define OUTF  128    // OUT

// Device scratch (no cudaMalloc allowed)
__device__ float  g_hs[(size_t)NSRC * HID];   // relu(h_src @ W1 + b1)
__device__ float  g_vs[(size_t)NDST * HID];   // scatter-sum of messages
__device__ float  g_ws[NDST];                 // scatter-sum of edge weights
__device__ double g_sumsq;                    // global sum of squares

// ---------------------------------------------------------------------------
// Kernel 0: zero the accumulators
// ---------------------------------------------------------------------------
__global__ void init_kernel() {
    int tid = blockIdx.x * blockDim.x + threadIdx.x;
    const int n4 = (NDST * HID) / 4;  // 1.6M float4
    if (tid < n4) ((float4*)g_vs)[tid] = make_float4(0.f, 0.f, 0.f, 0.f);
    if (tid < NDST) g_ws[tid] = 0.f;
    if (tid == 0) g_sumsq = 0.0;
}

// ---------------------------------------------------------------------------
// Kernel 1: g_hs = relu(h_src @ W1 + b1)    [100000 x 64] @ [64 x 64]
// Block: 256 threads, 64-row x 64-col tile. Thread: 4x4 accumulators.
// ---------------------------------------------------------------------------
__global__ __launch_bounds__(256) void gemm1_kernel(
    const float* __restrict__ hsrc,
    const float* __restrict__ W1,
    const float* __restrict__ b1)
{
    __shared__ float sW[HID * HID];   // [k][c] row-major, 16KB
    __shared__ float sX[64 * DF];     // [r][k], 16KB
    __shared__ float sB[HID];

    const int t = threadIdx.x;
    const int base = blockIdx.x * 64;

    // load W1 (4096 floats = 1024 float4)
    for (int i = t; i < (HID * HID) / 4; i += 256)
        ((float4*)sW)[i] = ((const float4*)W1)[i];
    if (t < HID) sB[t] = b1[t];

    // load X tile (64 rows x 64 cols), guard tail rows
    for (int i = t; i < (64 * DF) / 4; i += 256) {
        int r = i / (DF / 4);
        int row = base + r;
        float4 v = make_float4(0.f, 0.f, 0.f, 0.f);
        if (row < NSRC) v = ((const float4*)(hsrc + (size_t)row * DF))[i % (DF / 4)];
        ((float4*)sX)[i] = v;
    }
    __syncthreads();

    const int tx = t & 15;   // 16 col groups * 4 cols
    const int ty = t >> 4;   // 16 row groups * 4 rows

    float acc[4][4];
#pragma unroll
    for (int i = 0; i < 4; i++)
#pragma unroll
        for (int j = 0; j < 4; j++) acc[i][j] = 0.f;

#pragma unroll 8
    for (int k = 0; k < DF; k++) {
        float4 b = *(const float4*)(sW + k * HID + tx * 4);
        float a0 = sX[(ty * 4 + 0) * DF + k];
        float a1 = sX[(ty * 4 + 1) * DF + k];
        float a2 = sX[(ty * 4 + 2) * DF + k];
        float a3 = sX[(ty * 4 + 3) * DF + k];
        acc[0][0] += a0 * b.x; acc[0][1] += a0 * b.y; acc[0][2] += a0 * b.z; acc[0][3] += a0 * b.w;
        acc[1][0] += a1 * b.x; acc[1][1] += a1 * b.y; acc[1][2] += a1 * b.z; acc[1][3] += a1 * b.w;
        acc[2][0] += a2 * b.x; acc[2][1] += a2 * b.y; acc[2][2] += a2 * b.z; acc[2][3] += a2 * b.w;
        acc[3][0] += a3 * b.x; acc[3][1] += a3 * b.y; acc[3][2] += a3 * b.z; acc[3][3] += a3 * b.w;
    }

#pragma unroll
    for (int i = 0; i < 4; i++) {
        int row = base + ty * 4 + i;
        if (row < NSRC) {
            float4 o;
            o.x = fmaxf(acc[i][0] + sB[tx * 4 + 0], 0.f);
            o.y = fmaxf(acc[i][1] + sB[tx * 4 + 1], 0.f);
            o.z = fmaxf(acc[i][2] + sB[tx * 4 + 2], 0.f);
            o.w = fmaxf(acc[i][3] + sB[tx * 4 + 3], 0.f);
            ((float4*)(g_hs + (size_t)row * HID))[tx] = o;
        }
    }
}

// ---------------------------------------------------------------------------
// Kernel 2: edge scatter. 16 threads per edge, each owns a float4 slice.
//   g_vs[dst] += g_hs[src] * w   (red.global.add.v4.f32)
//   g_ws[dst] += w               (one lane per edge)
// ---------------------------------------------------------------------------
__global__ __launch_bounds__(256) void scatter_kernel(
    const int* __restrict__ src_idx,
    const int* __restrict__ dst_idx,
    const float* __restrict__ ew)
{
    int tid = blockIdx.x * 256 + threadIdx.x;
    int e = tid >> 4;
    if (e >= NEDGE) return;
    int p = tid & 15;

    int s = src_idx[e];
    int d = dst_idx[e];
    float w = ew[e];

    float4 v = *(const float4*)(g_hs + (size_t)s * HID + p * 4);
    v.x *= w; v.y *= w; v.z *= w; v.w *= w;

    float* dst = g_vs + (size_t)d * HID + p * 4;
    asm volatile("red.global.add.v4.f32 [%0], {%1, %2, %3, %4};"
                 :: "l"(dst), "f"(v.x), "f"(v.y), "f"(v.z), "f"(v.w)
                 : "memory");

    if (p == 0) atomicAdd(g_ws + d, w);
}

// ---------------------------------------------------------------------------
// Kernel 3: out = relu([vs/max(ws,1) || h_dst] @ W2 + b2); also accumulate
// global sum of squares. Block: 256 threads, 64-row x 128-col tile,
// thread: 8x4 accumulators. Dynamic smem: W2(64KB) + X(32KB) + b2.
// ---------------------------------------------------------------------------
__global__ __launch_bounds__(256) void gemm2_kernel(
    const float* __restrict__ hdst,
    const float* __restrict__ W2,
    const float* __restrict__ b2,
    float* __restrict__ out)
{
    extern __shared__ float sm[];
    float* sW = sm;                      // 128*128 = 16384 floats
    float* sX = sm + 128 * 128;          // 64*128  =  8192 floats
    float* sB = sX + 64 * 128;           // 128 floats

    const int t = threadIdx.x;
    const int base = blockIdx.x * 64;

    // load W2 (16384 floats = 4096 float4)
    for (int i = t; i < (128 * 128) / 4; i += 256)
        ((float4*)sW)[i] = ((const float4*)W2)[i];
    if (t < 128) sB[t] = b2[t];

    // build X tile: cols 0..63 = vs/max(ws,1), cols 64..127 = h_dst
    for (int i = t; i < 64 * 128; i += 256) {
        int r = i >> 7;
        int c = i & 127;
        int row = base + r;
        float v = 0.f;
        if (row < NDST) {
            if (c < 64) {
                float w = fmaxf(g_ws[row], 1.f);
                v = g_vs[(size_t)row * 64 + c] / w;
            } else {
                v = hdst[(size_t)row * 64 + (c - 64)];
            }
        }
        sX[i] = v;
    }
    __syncthreads();

    const int tx = t & 31;   // 32 col groups * 4 cols = 128
    const int ty = t >> 5;   // 8 row groups * 8 rows = 64

    float acc[8][4];
#pragma unroll
    for (int i = 0; i < 8; i++)
#pragma unroll
        for (int j = 0; j < 4; j++) acc[i][j] = 0.f;

#pragma unroll 8
    for (int k = 0; k < 128; k++) {
        float4 b = *(const float4*)(sW + k * 128 + tx * 4);
#pragma unroll
        for (int i = 0; i < 8; i++) {
            float a = sX[(ty * 8 + i) * 128 + k];  // broadcast within warp
            acc[i][0] += a * b.x;
            acc[i][1] += a * b.y;
            acc[i][2] += a * b.z;
            acc[i][3] += a * b.w;
        }
    }

    // bias + relu + store + local sum of squares
    float ss = 0.f;
    float bb0 = sB[tx * 4 + 0], bb1 = sB[tx * 4 + 1];
    float bb2 = sB[tx * 4 + 2], bb3 = sB[tx * 4 + 3];
#pragma unroll
    for (int i = 0; i < 8; i++) {
        int row = base + ty * 8 + i;
        if (row < NDST) {
            float4 o;
            o.x = fmaxf(acc[i][0] + bb0, 0.f);
            o.y = fmaxf(acc[i][1] + bb1, 0.f);
            o.z = fmaxf(acc[i][2] + bb2, 0.f);
            o.w = fmaxf(acc[i][3] + bb3, 0.f);
            ((float4*)(out + (size_t)row * OUTF))[tx] = o;
            ss += o.x * o.x + o.y * o.y + o.z * o.z + o.w * o.w;
        }
    }

    // block reduction of ss (reuse sX region as scratch)
    __syncthreads();
    sX[t] = ss;
    __syncthreads();
#pragma unroll
    for (int off = 128; off > 0; off >>= 1) {
        if (t < off) sX[t] += sX[t + off];
        __syncthreads();
    }
    if (t == 0) atomicAdd(&g_sumsq, (double)sX[0]);
}

// ---------------------------------------------------------------------------
// Kernel 4: out *= 1/sqrt(sumsq)
// ---------------------------------------------------------------------------
__global__ __launch_bounds__(256) void scale_kernel(float* __restrict__ out) {
    int tid = blockIdx.x * 256 + threadIdx.x;
    const int n4 = (NDST * OUTF) / 4;  // 3.2M
    if (tid >= n4) return;
    float s = (float)(1.0 / sqrt(g_sumsq));
    float4 v = ((float4*)out)[tid];
    v.x *= s; v.y *= s; v.z *= s; v.w *= s;
    ((float4*)out)[tid] = v;
}

// ---------------------------------------------------------------------------
// Launch: init -> gemm1 -> scatter -> gemm2 -> scale  (default stream order)
// ---------------------------------------------------------------------------
extern "C" void kernel_launch(void* const* d_in, const int* in_sizes, int n_in,
                              void* d_out, int out_size) {
    const float* h_src = (const float*)d_in[0];
    const float* h_dst = (const float*)d_in[1];
    const float* ew    = (const float*)d_in[2];
    const float* W1    = (const float*)d_in[3];
    const float* b1    = (const float*)d_in[4];
    const float* W2    = (const float*)d_in[5];
    const float* b2    = (const float*)d_in[6];
    const int*   srci  = (const int*)d_in[7];
    const int*   dsti  = (const int*)d_in[8];
    float* out = (float*)d_out;

    // dynamic smem for gemm2: W2 + X tile + b2
    static const int smem2 = (128 * 128 + 64 * 128 + 128) * (int)sizeof(float);
    cudaFuncSetAttribute(gemm2_kernel,
                         cudaFuncAttributeMaxDynamicSharedMemorySize, smem2);

    // 0) zero accumulators: cover 1.6M float4 for vs, NDST for ws
    init_kernel<<<(NDST * HID / 4 + 255) / 256, 256>>>();

    // 1) hs = relu(h_src @ W1 + b1)
    gemm1_kernel<<<(NSRC + 63) / 64, 256>>>(h_src, W1, b1);

    // 2) edge scatter (16 threads / edge)
    {
        long long threads = (long long)NEDGE * 16;
        int blocks = (int)((threads + 255) / 256);
        scatter_kernel<<<blocks, 256>>>(srci, dsti, ew);
    }

    // 3) out = relu([nv || h_dst] @ W2 + b2), accumulate sumsq
    gemm2_kernel<<<(NDST + 63) / 64, 256, smem2>>>(h_dst, W2, b2, out);

    // 4) global L2 normalization
    scale_kernel<<<(NDST * OUTF / 4 + 255) / 256, 256>>>(out);
}